// round 14
// baseline (speedup 1.0000x reference)
#include <cuda_runtime.h>
#include <cuda_bf16.h>
#include <cstdint>

#define NB 4
#define NN 4096
#define NC 128
#define NKCH 3
#define LRF ((float)(2.0 / (2.0 + 1e-06)))

// ---------------------------------------------------------------------------
// Device scratch. g_Z is [b][k][n][c] contiguous, so the torch
// .view(B,N,-1) of stacked [B,K,N,C] == per-batch rows at stride 384.
// ---------------------------------------------------------------------------
__device__ float         g_Z[(size_t)NB * NKCH * NN * NC];   // 24 MB fp32
__device__ __nv_bfloat16 g_adjh[(size_t)NB * NN * NN];       // 128 MB bf16 adj
__device__ __nv_bfloat16 g_xh[(size_t)NB * NN * NC];         // 4 MB bf16 x
__device__ __nv_bfloat16 g_t1h[(size_t)NB * NN * NC];        // 4 MB bf16 T1
__device__ float g_degpart[16 * NB * NN];
__device__ float g_deg[NB * NN];

// ---------------------------------------------------------------------------
// degree[b,n] = sum_m adj[b,m,n] (exact fp32, deterministic 2-stage),
// fused with adj fp32 -> bf16 conversion (adj is streamed here anyway).
// ---------------------------------------------------------------------------
__global__ void degree_partial_cvt_kernel(const float* __restrict__ adj) {
    const int b   = blockIdx.z;
    const int col = blockIdx.x * 128 + threadIdx.x;
    const int r0  = blockIdx.y * 256;
    const float* A = adj + (size_t)b * NN * NN;
    __nv_bfloat16* Ah = g_adjh + (size_t)b * NN * NN;
    float s = 0.f;
#pragma unroll 4
    for (int m = 0; m < 256; ++m) {
        const float v = A[(size_t)(r0 + m) * NN + col];
        s += v;
        Ah[(size_t)(r0 + m) * NN + col] = __float2bfloat16(v);
    }
    g_degpart[(size_t)blockIdx.y * NB * NN + b * NN + col] = s;
}

__global__ void degree_reduce_kernel() {
    int i = blockIdx.x * blockDim.x + threadIdx.x;
    if (i < NB * NN) {
        float s = 0.f;
#pragma unroll
        for (int r = 0; r < 16; ++r)
            s += g_degpart[(size_t)r * NB * NN + i];
        g_deg[i] = s;
    }
}

// x -> bf16
__global__ void x_cvt_kernel(const float* __restrict__ x) {
    int i = blockIdx.x * blockDim.x + threadIdx.x;
    if (i < NB * NN * NC) g_xh[i] = __float2bfloat16(x[i]);
}

// ---------------------------------------------------------------------------
// Fused Chebyshev step via mma.sync bf16 (m16n8k16, fp32 accumulate):
//   acc = adj[rows] @ Zin                (bf16 inputs, fp32 accum)
//   Zout[n,c] = alpha*( LRF*(deg[n]*Zin_f32[n,c] - acc) - Zin_f32 ) + beta*x
// step 0: B = g_xh,  Zin_f32 = x,      out -> slice1 (+ x -> slice0, T1 -> g_t1h)
// step 1: B = g_t1h, Zin_f32 = slice1, out -> slice2
//
// 256 threads (8 warps, 2m x 4n), CTA tile 128x128, warp tile 64x32,
// K chunk 64 (4 k16 steps), 5-stage cp.async ring.
// A smem: [m][k] bf16, pitch 72 bf16 (144 B)  -> LDS.32 banks 4g+tig (CF)
// B smem: [k][n] bf16, pitch 136 bf16 (272 B) -> ldmatrix rows banks 4k (CF)
// ---------------------------------------------------------------------------
#define PA 72                         // bf16 units per A row
#define PB 136                        // bf16 units per B row
#define A_BYTES (128 * PA * 2)        // 18432
#define STG (A_BYTES + 64 * PB * 2)   // 35840
#define NST 5
#define NCH 64

__device__ __forceinline__ void mma_bf16_16x8x16(
    float* d, uint32_t a0, uint32_t a1, uint32_t a2, uint32_t a3,
    uint32_t b0, uint32_t b1)
{
    asm volatile(
        "mma.sync.aligned.m16n8k16.row.col.f32.bf16.bf16.f32 "
        "{%0,%1,%2,%3}, {%4,%5,%6,%7}, {%8,%9}, {%0,%1,%2,%3};"
        : "+f"(d[0]), "+f"(d[1]), "+f"(d[2]), "+f"(d[3])
        : "r"(a0), "r"(a1), "r"(a2), "r"(a3), "r"(b0), "r"(b1));
}

__global__ __launch_bounds__(256, 1)
void cheb_mma_kernel(const float* __restrict__ x, int step)
{
    extern __shared__ char dsm[];

    const int b    = blockIdx.y;
    const int row0 = blockIdx.x * 128;
    const int tid  = threadIdx.x;
    const int wid  = tid >> 5;
    const int lid  = tid & 31;
    const int g    = lid >> 2;
    const int tig  = lid & 3;
    const int mbase = (wid & 1) * 64;
    const int nbase = (wid >> 1) * 32;

    const __nv_bfloat16* Arowh = g_adjh + (size_t)b * NN * NN + (size_t)row0 * NN;
    const __nv_bfloat16* Binh  = (step == 0 ? g_xh : g_t1h) + (size_t)b * NN * NC;
    const float* Xb = x + (size_t)b * NN * NC;
    float* Zbase = g_Z + (size_t)b * NKCH * NN * NC;
    const float* Zin_f = (step == 0) ? Xb : (Zbase + (size_t)1 * NN * NC);
    float* Zout = (step == 0) ? (Zbase + (size_t)1 * NN * NC)
                              : (Zbase + (size_t)2 * NN * NC);
    float* Z0 = Zbase;
    __nv_bfloat16* T1h = g_t1h + (size_t)b * NN * NC;
    const float alpha = (step == 0) ? 1.f : 2.f;
    const float beta  = (step == 0) ? 0.f : -1.f;

    uint32_t smem0;
    asm("{ .reg .u64 t; cvta.to.shared.u64 t, %1; cvt.u32.u64 %0, t; }"
        : "=r"(smem0) : "l"(dsm));

    float acc[4][4][4];
#pragma unroll
    for (int mt = 0; mt < 4; ++mt)
#pragma unroll
        for (int nt = 0; nt < 4; ++nt)
#pragma unroll
            for (int q = 0; q < 4; ++q) acc[mt][nt][q] = 0.f;

    auto issue_chunk = [&](int chunk) {
        const uint32_t stg = smem0 + (uint32_t)(chunk % NST) * STG;
        const int k0 = chunk * 64;
        // A: 128 rows x 64 bf16 (128B) = 1024 x 16B chunks, 4/thread
#pragma unroll
        for (int it = 0; it < 4; ++it) {
            const int idx = tid + it * 256;
            const int r = idx >> 3, q = idx & 7;
            const uint32_t da = stg + (uint32_t)r * (PA * 2) + q * 16;
            const __nv_bfloat16* src = Arowh + (size_t)r * NN + k0 + q * 8;
            asm volatile("cp.async.cg.shared.global [%0], [%1], 16;"
                         :: "r"(da), "l"(src));
        }
        // B: 64 rows x 128 bf16 (256B) = 1024 x 16B chunks, 4/thread
#pragma unroll
        for (int it = 0; it < 4; ++it) {
            const int idx = tid + it * 256;
            const int r = idx >> 4, q = idx & 15;
            const uint32_t db = stg + A_BYTES + (uint32_t)r * (PB * 2) + q * 16;
            const __nv_bfloat16* src = Binh + (size_t)(k0 + r) * NC + q * 8;
            asm volatile("cp.async.cg.shared.global [%0], [%1], 16;"
                         :: "r"(db), "l"(src));
        }
        asm volatile("cp.async.commit_group;" ::: "memory");
    };

    issue_chunk(0); issue_chunk(1); issue_chunk(2); issue_chunk(3);

    const int rowsel = lid & 15;

    for (int c = 0; c < NCH; ++c) {
        if (c <= NCH - 4)      asm volatile("cp.async.wait_group 3;" ::: "memory");
        else if (c == NCH - 3) asm volatile("cp.async.wait_group 2;" ::: "memory");
        else if (c == NCH - 2) asm volatile("cp.async.wait_group 1;" ::: "memory");
        else                   asm volatile("cp.async.wait_group 0;" ::: "memory");
        __syncthreads();

        if (c + 4 < NCH) issue_chunk(c + 4);

        const uint32_t stg = smem0 + (uint32_t)(c % NST) * STG;
        const uint32_t* As32 = (const uint32_t*)(dsm + (size_t)(c % NST) * STG);
        const uint32_t bbase = stg + A_BYTES + (uint32_t)rowsel * (PB * 2);

#pragma unroll
        for (int ks = 0; ks < 4; ++ks) {
            // A fragments: packed bf16 pairs, one LDS.32 each
            uint32_t a[4][4];
#pragma unroll
            for (int mt = 0; mt < 4; ++mt) {
                const int i0 = mbase + mt * 16 + g;
                const int kw = ks * 8 + tig;          // (ks*16 + 2*tig)/2
                a[mt][0] = As32[(i0)     * (PA / 2) + kw];
                a[mt][1] = As32[(i0 + 8) * (PA / 2) + kw];
                a[mt][2] = As32[(i0)     * (PA / 2) + kw + 4];
                a[mt][3] = As32[(i0 + 8) * (PA / 2) + kw + 4];
            }
#pragma unroll
            for (int nt = 0; nt < 4; ++nt) {
                const int j0 = nbase + nt * 8;
                uint32_t b0, b1;
                const uint32_t baddr = bbase + (uint32_t)(ks * 16) * (PB * 2) + j0 * 2;
                asm volatile(
                    "ldmatrix.sync.aligned.m8n8.x2.trans.shared.b16 {%0, %1}, [%2];"
                    : "=r"(b0), "=r"(b1) : "r"(baddr));
#pragma unroll
                for (int mt = 0; mt < 4; ++mt)
                    mma_bf16_16x8x16(acc[mt][nt], a[mt][0], a[mt][1], a[mt][2], a[mt][3], b0, b1);
            }
        }
        __syncthreads();
    }

    // Fused epilogue (fp32 Zin for the exact deg*z term)
#pragma unroll
    for (int mt = 0; mt < 4; ++mt) {
        const int r0 = row0 + mbase + mt * 16 + g;
        const int r1 = r0 + 8;
        const float dg0 = g_deg[b * NN + r0];
        const float dg1 = g_deg[b * NN + r1];
#pragma unroll
        for (int nt = 0; nt < 4; ++nt) {
            const int c0 = nbase + nt * 8 + 2 * tig;
            const float2 z0 = *(const float2*)(Zin_f + (size_t)r0 * NC + c0);
            const float2 z1 = *(const float2*)(Zin_f + (size_t)r1 * NC + c0);
            float2 o0, o1;
            o0.x = alpha * (LRF * (dg0 * z0.x - acc[mt][nt][0]) - z0.x);
            o0.y = alpha * (LRF * (dg0 * z0.y - acc[mt][nt][1]) - z0.y);
            o1.x = alpha * (LRF * (dg1 * z1.x - acc[mt][nt][2]) - z1.x);
            o1.y = alpha * (LRF * (dg1 * z1.y - acc[mt][nt][3]) - z1.y);
            if (beta != 0.f) {
                const float2 x0 = *(const float2*)(Xb + (size_t)r0 * NC + c0);
                const float2 x1 = *(const float2*)(Xb + (size_t)r1 * NC + c0);
                o0.x += beta * x0.x; o0.y += beta * x0.y;
                o1.x += beta * x1.x; o1.y += beta * x1.y;
            }
            *(float2*)(Zout + (size_t)r0 * NC + c0) = o0;
            *(float2*)(Zout + (size_t)r1 * NC + c0) = o1;
            if (step == 0) {
                *(float2*)(Z0 + (size_t)r0 * NC + c0) = z0;
                *(float2*)(Z0 + (size_t)r1 * NC + c0) = z1;
                // bf16 T1 for next step's B operand
                __nv_bfloat162 h0; h0.x = __float2bfloat16(o0.x); h0.y = __float2bfloat16(o0.y);
                __nv_bfloat162 h1; h1.x = __float2bfloat16(o1.x); h1.y = __float2bfloat16(o1.y);
                *(__nv_bfloat162*)(T1h + (size_t)r0 * NC + c0) = h0;
                *(__nv_bfloat162*)(T1h + (size_t)r1 * NC + c0) = h1;
            }
        }
    }
}

// ---------------------------------------------------------------------------
// Final linear: out[b,n,o] = sum_{f<384} Zr[b,n,f] * W[o,f]
//   Zr = per-batch flat g_Z buffer read as rows of stride 384 (view trick).
// ---------------------------------------------------------------------------
__global__ __launch_bounds__(256, 1)
void out_gemm_kernel(const float* __restrict__ W, float* __restrict__ out)
{
    const int b    = blockIdx.y;
    const int row0 = blockIdx.x * 128;
    const float* Zr = g_Z + (size_t)b * NKCH * NN * NC + (size_t)row0 * 384;

    __shared__ float As[8][128];
    __shared__ float Bs[8][128];

    const int tid  = threadIdx.x;
    const int tx   = tid & 15;
    const int ty   = tid >> 4;
    const int aRow = tid >> 1;
    const int aCol = (tid & 1) << 2;

    float acc[8][8];
#pragma unroll
    for (int i = 0; i < 8; ++i)
#pragma unroll
        for (int j = 0; j < 8; ++j) acc[i][j] = 0.f;

    float4 av = *(const float4*)(Zr + (size_t)aRow * 384 + aCol);
    float bv[4];
#pragma unroll
    for (int e = 0; e < 4; ++e) {
        const int lin = tid + e * 256;
        bv[e] = W[(size_t)(lin & 127) * 384 + (lin >> 7)];
    }

    for (int k0 = 0; k0 < 384; k0 += 8) {
        As[aCol + 0][aRow] = av.x;
        As[aCol + 1][aRow] = av.y;
        As[aCol + 2][aRow] = av.z;
        As[aCol + 3][aRow] = av.w;
#pragma unroll
        for (int e = 0; e < 4; ++e) {
            const int lin = tid + e * 256;
            Bs[lin >> 7][lin & 127] = bv[e];
        }
        __syncthreads();

        if (k0 + 8 < 384) {
            av = *(const float4*)(Zr + (size_t)aRow * 384 + (k0 + 8) + aCol);
#pragma unroll
            for (int e = 0; e < 4; ++e) {
                const int lin = tid + e * 256;
                bv[e] = W[(size_t)(lin & 127) * 384 + (k0 + 8) + (lin >> 7)];
            }
        }

#pragma unroll
        for (int kk = 0; kk < 8; ++kk) {
            float a[8], bb[8];
            *(float4*)&a[0]  = *(const float4*)&As[kk][ty * 4];
            *(float4*)&a[4]  = *(const float4*)&As[kk][64 + ty * 4];
            *(float4*)&bb[0] = *(const float4*)&Bs[kk][tx * 4];
            *(float4*)&bb[4] = *(const float4*)&Bs[kk][64 + tx * 4];
#pragma unroll
            for (int i = 0; i < 8; ++i)
#pragma unroll
                for (int j = 0; j < 8; ++j)
                    acc[i][j] += a[i] * bb[j];
        }
        __syncthreads();
    }

#pragma unroll
    for (int i = 0; i < 8; ++i) {
        const int r = (i < 4) ? (ty * 4 + i) : (64 + ty * 4 + (i - 4));
        const int n = row0 + r;
#pragma unroll
        for (int jh = 0; jh < 2; ++jh) {
            const int c = (jh == 0) ? (tx * 4) : (64 + tx * 4);
            float4 res;
            res.x = acc[i][jh * 4 + 0];
            res.y = acc[i][jh * 4 + 1];
            res.z = acc[i][jh * 4 + 2];
            res.w = acc[i][jh * 4 + 3];
            *(float4*)(out + ((size_t)b * NN + n) * NC + c) = res;
        }
    }
}

// ---------------------------------------------------------------------------
extern "C" void kernel_launch(void* const* d_in, const int* in_sizes, int n_in,
                              void* d_out, int out_size) {
    const float* x   = (const float*)d_in[0];   // [4,4096,128]
    const float* adj = (const float*)d_in[1];   // [4,4096,4096]
    const float* W   = (const float*)d_in[2];   // [128,384]
    float* out = (float*)d_out;

    (void)in_sizes; (void)n_in; (void)out_size;

    const int SMEM_CHEB = NST * STG;            // 179200 B
    cudaFuncSetAttribute(cheb_mma_kernel,
                         cudaFuncAttributeMaxDynamicSharedMemorySize, SMEM_CHEB);

    degree_partial_cvt_kernel<<<dim3(NN / 128, 16, NB), 128>>>(adj);
    degree_reduce_kernel<<<(NB * NN + 255) / 256, 256>>>();
    x_cvt_kernel<<<(NB * NN * NC + 255) / 256, 256>>>(x);

    // T1 = LR*(deg*x - adj@x) - x       (stashes x->slice0 and T1->bf16)
    cheb_mma_kernel<<<dim3(NN / 128, NB), 256, SMEM_CHEB>>>(x, 0);
    // T2 = 2*(LR*(deg*T1 - adj@T1) - T1) - x
    cheb_mma_kernel<<<dim3(NN / 128, NB), 256, SMEM_CHEB>>>(x, 1);

    out_gemm_kernel<<<dim3(NN / 128, NB), 256>>>(W, out);
}

// round 16
// speedup vs baseline: 1.3813x; 1.3813x over previous
#include <cuda_runtime.h>
#include <cuda_bf16.h>
#include <cstdint>

#define NB 4
#define NN 4096
#define NC 128
#define NKCH 3
#define LRF ((float)(2.0 / (2.0 + 1e-06)))

// ---------------------------------------------------------------------------
// Device scratch. g_Z is [b][k][n][c] contiguous, so the torch
// .view(B,N,-1) of stacked [B,K,N,C] == per-batch rows at stride 384.
// ---------------------------------------------------------------------------
__device__ float         g_Z[(size_t)NB * NKCH * NN * NC];   // 24 MB fp32
__device__ __nv_bfloat16 g_adjh[(size_t)NB * NN * NN];       // 128 MB bf16 adj
__device__ __nv_bfloat16 g_xh[(size_t)NB * NN * NC];         // 4 MB bf16 x
__device__ __nv_bfloat16 g_t1h[(size_t)NB * NN * NC];        // 4 MB bf16 T1
__device__ float g_degpart[16 * NB * NN];
__device__ float g_deg[NB * NN];

// ---------------------------------------------------------------------------
// degree[b,n] = sum_m adj[b,m,n] (exact fp32, deterministic 2-stage),
// fused with adj fp32 -> bf16 conversion (adj is streamed here anyway).
// ---------------------------------------------------------------------------
__global__ void degree_partial_cvt_kernel(const float* __restrict__ adj) {
    const int b   = blockIdx.z;
    const int col = blockIdx.x * 128 + threadIdx.x;
    const int r0  = blockIdx.y * 256;
    const float* A = adj + (size_t)b * NN * NN;
    __nv_bfloat16* Ah = g_adjh + (size_t)b * NN * NN;
    float s = 0.f;
#pragma unroll 8
    for (int m = 0; m < 256; ++m) {
        const float v = A[(size_t)(r0 + m) * NN + col];
        s += v;
        Ah[(size_t)(r0 + m) * NN + col] = __float2bfloat16(v);
    }
    g_degpart[(size_t)blockIdx.y * NB * NN + b * NN + col] = s;
}

__global__ void degree_reduce_kernel() {
    int i = blockIdx.x * blockDim.x + threadIdx.x;
    if (i < NB * NN) {
        float s = 0.f;
#pragma unroll
        for (int r = 0; r < 16; ++r)
            s += g_degpart[(size_t)r * NB * NN + i];
        g_deg[i] = s;
    }
}

// x -> bf16
__global__ void x_cvt_kernel(const float* __restrict__ x) {
    int i = blockIdx.x * blockDim.x + threadIdx.x;
    if (i < NB * NN * NC) g_xh[i] = __float2bfloat16(x[i]);
}

// ---------------------------------------------------------------------------
// Fused Chebyshev step via mma.sync bf16 (m16n8k16, fp32 accumulate):
//   acc = adj[rows] @ Zin                (bf16 inputs, fp32 accum)
//   Zout[n,c] = alpha*( LRF*(deg[n]*Zin_f32[n,c] - acc) - Zin_f32 ) + beta*x
//
// CTA tile 64(m) x 128(c), 256 threads (8 warps, 2m x 4n), warp tile 32x32.
// K chunk 64 (4 k16 steps), 4-stage cp.async ring, 2 CTAs/SM.
// A smem: [m][k] bf16, pitch 72 (144 B) -> LDS.32 banks 4g+tig+8ks (CF)
// B smem: [k][n] bf16, pitch 136 (272 B) -> ldmatrix rows banks 4k (CF)
// ---------------------------------------------------------------------------
#define TM 64                         // CTA rows
#define PA 72                         // bf16 units per A row
#define PB 136                        // bf16 units per B row
#define A_BYTES (TM * PA * 2)         // 9216
#define STG (A_BYTES + 64 * PB * 2)   // 26624
#define NST 4
#define NCH 64

__device__ __forceinline__ void mma_bf16_16x8x16(
    float* d, uint32_t a0, uint32_t a1, uint32_t a2, uint32_t a3,
    uint32_t b0, uint32_t b1)
{
    asm volatile(
        "mma.sync.aligned.m16n8k16.row.col.f32.bf16.bf16.f32 "
        "{%0,%1,%2,%3}, {%4,%5,%6,%7}, {%8,%9}, {%0,%1,%2,%3};"
        : "+f"(d[0]), "+f"(d[1]), "+f"(d[2]), "+f"(d[3])
        : "r"(a0), "r"(a1), "r"(a2), "r"(a3), "r"(b0), "r"(b1));
}

__global__ __launch_bounds__(256, 2)
void cheb_mma_kernel(const float* __restrict__ x, int step)
{
    extern __shared__ char dsm[];

    const int b    = blockIdx.y;
    const int row0 = blockIdx.x * TM;
    const int tid  = threadIdx.x;
    const int wid  = tid >> 5;
    const int lid  = tid & 31;
    const int g    = lid >> 2;
    const int tig  = lid & 3;
    const int mbase = (wid & 1) * 32;        // 2 warps along M
    const int nbase = (wid >> 1) * 32;       // 4 warps along N

    const __nv_bfloat16* Arowh = g_adjh + (size_t)b * NN * NN + (size_t)row0 * NN;
    const __nv_bfloat16* Binh  = (step == 0 ? g_xh : g_t1h) + (size_t)b * NN * NC;
    const float* Xb = x + (size_t)b * NN * NC;
    float* Zbase = g_Z + (size_t)b * NKCH * NN * NC;
    const float* Zin_f = (step == 0) ? Xb : (Zbase + (size_t)1 * NN * NC);
    float* Zout = (step == 0) ? (Zbase + (size_t)1 * NN * NC)
                              : (Zbase + (size_t)2 * NN * NC);
    float* Z0 = Zbase;
    __nv_bfloat16* T1h = g_t1h + (size_t)b * NN * NC;
    const float alpha = (step == 0) ? 1.f : 2.f;
    const float beta  = (step == 0) ? 0.f : -1.f;

    uint32_t smem0;
    asm("{ .reg .u64 t; cvta.to.shared.u64 t, %1; cvt.u32.u64 %0, t; }"
        : "=r"(smem0) : "l"(dsm));

    float acc[2][4][4];
#pragma unroll
    for (int mt = 0; mt < 2; ++mt)
#pragma unroll
        for (int nt = 0; nt < 4; ++nt)
#pragma unroll
            for (int q = 0; q < 4; ++q) acc[mt][nt][q] = 0.f;

    auto issue_chunk = [&](int chunk) {
        const uint32_t stg = smem0 + (uint32_t)(chunk & (NST - 1)) * STG;
        const int k0 = chunk * 64;
        // A: 64 rows x 64 bf16 (128B) = 512 x 16B chunks, 2/thread
#pragma unroll
        for (int it = 0; it < 2; ++it) {
            const int idx = tid + it * 256;
            const int r = idx >> 3, q = idx & 7;
            const uint32_t da = stg + (uint32_t)r * (PA * 2) + q * 16;
            const __nv_bfloat16* src = Arowh + (size_t)r * NN + k0 + q * 8;
            asm volatile("cp.async.cg.shared.global [%0], [%1], 16;"
                         :: "r"(da), "l"(src));
        }
        // B: 64 rows x 128 bf16 (256B) = 1024 x 16B chunks, 4/thread
#pragma unroll
        for (int it = 0; it < 4; ++it) {
            const int idx = tid + it * 256;
            const int r = idx >> 4, q = idx & 15;
            const uint32_t db = stg + A_BYTES + (uint32_t)r * (PB * 2) + q * 16;
            const __nv_bfloat16* src = Binh + (size_t)(k0 + r) * NC + q * 8;
            asm volatile("cp.async.cg.shared.global [%0], [%1], 16;"
                         :: "r"(db), "l"(src));
        }
        asm volatile("cp.async.commit_group;" ::: "memory");
    };

    issue_chunk(0); issue_chunk(1); issue_chunk(2);

    const int rowsel = lid & 15;

    for (int c = 0; c < NCH; ++c) {
        if (c < NCH - 2)       asm volatile("cp.async.wait_group 2;" ::: "memory");
        else if (c == NCH - 2) asm volatile("cp.async.wait_group 1;" ::: "memory");
        else                   asm volatile("cp.async.wait_group 0;" ::: "memory");
        __syncthreads();

        if (c + 3 < NCH) issue_chunk(c + 3);

        const uint32_t stg = smem0 + (uint32_t)(c & (NST - 1)) * STG;
        const uint32_t* As32 = (const uint32_t*)(dsm + (size_t)(c & (NST - 1)) * STG);
        const uint32_t bbase = stg + A_BYTES + (uint32_t)rowsel * (PB * 2);

#pragma unroll
        for (int ks = 0; ks < 4; ++ks) {
            uint32_t a[2][4];
#pragma unroll
            for (int mt = 0; mt < 2; ++mt) {
                const int i0 = mbase + mt * 16 + g;
                const int kw = ks * 8 + tig;
                a[mt][0] = As32[(i0)     * (PA / 2) + kw];
                a[mt][1] = As32[(i0 + 8) * (PA / 2) + kw];
                a[mt][2] = As32[(i0)     * (PA / 2) + kw + 4];
                a[mt][3] = As32[(i0 + 8) * (PA / 2) + kw + 4];
            }
#pragma unroll
            for (int nt = 0; nt < 4; ++nt) {
                const int j0 = nbase + nt * 8;
                uint32_t b0, b1;
                const uint32_t baddr = bbase + (uint32_t)(ks * 16) * (PB * 2) + j0 * 2;
                asm volatile(
                    "ldmatrix.sync.aligned.m8n8.x2.trans.shared.b16 {%0, %1}, [%2];"
                    : "=r"(b0), "=r"(b1) : "r"(baddr));
#pragma unroll
                for (int mt = 0; mt < 2; ++mt)
                    mma_bf16_16x8x16(acc[mt][nt], a[mt][0], a[mt][1], a[mt][2], a[mt][3], b0, b1);
            }
        }
    }

    // Fused epilogue (fp32 Zin for the exact deg*z term)
#pragma unroll
    for (int mt = 0; mt < 2; ++mt) {
        const int r0 = row0 + mbase + mt * 16 + g;
        const int r1 = r0 + 8;
        const float dg0 = g_deg[b * NN + r0];
        const float dg1 = g_deg[b * NN + r1];
#pragma unroll
        for (int nt = 0; nt < 4; ++nt) {
            const int c0 = nbase + nt * 8 + 2 * tig;
            const float2 z0 = *(const float2*)(Zin_f + (size_t)r0 * NC + c0);
            const float2 z1 = *(const float2*)(Zin_f + (size_t)r1 * NC + c0);
            float2 o0, o1;
            o0.x = alpha * (LRF * (dg0 * z0.x - acc[mt][nt][0]) - z0.x);
            o0.y = alpha * (LRF * (dg0 * z0.y - acc[mt][nt][1]) - z0.y);
            o1.x = alpha * (LRF * (dg1 * z1.x - acc[mt][nt][2]) - z1.x);
            o1.y = alpha * (LRF * (dg1 * z1.y - acc[mt][nt][3]) - z1.y);
            if (beta != 0.f) {
                const float2 x0 = *(const float2*)(Xb + (size_t)r0 * NC + c0);
                const float2 x1 = *(const float2*)(Xb + (size_t)r1 * NC + c0);
                o0.x += beta * x0.x; o0.y += beta * x0.y;
                o1.x += beta * x1.x; o1.y += beta * x1.y;
            }
            *(float2*)(Zout + (size_t)r0 * NC + c0) = o0;
            *(float2*)(Zout + (size_t)r1 * NC + c0) = o1;
            if (step == 0) {
                *(float2*)(Z0 + (size_t)r0 * NC + c0) = z0;
                *(float2*)(Z0 + (size_t)r1 * NC + c0) = z1;
                __nv_bfloat162 h0; h0.x = __float2bfloat16(o0.x); h0.y = __float2bfloat16(o0.y);
                __nv_bfloat162 h1; h1.x = __float2bfloat16(o1.x); h1.y = __float2bfloat16(o1.y);
                *(__nv_bfloat162*)(T1h + (size_t)r0 * NC + c0) = h0;
                *(__nv_bfloat162*)(T1h + (size_t)r1 * NC + c0) = h1;
            }
        }
    }
}

// ---------------------------------------------------------------------------
// Final linear: out[b,n,o] = sum_{f<384} Zr[b,n,f] * W[o,f]
//   Zr = per-batch flat g_Z buffer read as rows of stride 384 (view trick).
// 64-row tiles, 128 threads, small smem -> multiple CTAs/SM.
// ---------------------------------------------------------------------------
__global__ __launch_bounds__(128)
void out_gemm_kernel(const float* __restrict__ W, float* __restrict__ out)
{
    const int b    = blockIdx.y;
    const int row0 = blockIdx.x * 64;
    const float* Zr = g_Z + (size_t)b * NKCH * NN * NC + (size_t)row0 * 384;

    __shared__ float As[8][64];
    __shared__ float Bs[8][128];

    const int tid  = threadIdx.x;
    const int tx   = tid & 15;
    const int ty   = tid >> 4;
    const int aRow = tid >> 1;             // 0..63
    const int aCol = (tid & 1) << 2;       // 0 or 4

    float acc[8][8];
#pragma unroll
    for (int i = 0; i < 8; ++i)
#pragma unroll
        for (int j = 0; j < 8; ++j) acc[i][j] = 0.f;

    float4 av = *(const float4*)(Zr + (size_t)aRow * 384 + aCol);
    float bv[8];
#pragma unroll
    for (int e = 0; e < 8; ++e) {
        const int lin = tid + e * 128;
        bv[e] = W[(size_t)(lin & 127) * 384 + (lin >> 7)];
    }

    for (int k0 = 0; k0 < 384; k0 += 8) {
        As[aCol + 0][aRow] = av.x;
        As[aCol + 1][aRow] = av.y;
        As[aCol + 2][aRow] = av.z;
        As[aCol + 3][aRow] = av.w;
#pragma unroll
        for (int e = 0; e < 8; ++e) {
            const int lin = tid + e * 128;
            Bs[lin >> 7][lin & 127] = bv[e];
        }
        __syncthreads();

        if (k0 + 8 < 384) {
            av = *(const float4*)(Zr + (size_t)aRow * 384 + (k0 + 8) + aCol);
#pragma unroll
            for (int e = 0; e < 8; ++e) {
                const int lin = tid + e * 128;
                bv[e] = W[(size_t)(lin & 127) * 384 + (k0 + 8) + (lin >> 7)];
            }
        }

#pragma unroll
        for (int kk = 0; kk < 8; ++kk) {
            float a[8], bb[8];
            *(float4*)&a[0]  = *(const float4*)&As[kk][ty * 4];
            *(float4*)&a[4]  = *(const float4*)&As[kk][32 + ty * 4];
            *(float4*)&bb[0] = *(const float4*)&Bs[kk][tx * 4];
            *(float4*)&bb[4] = *(const float4*)&Bs[kk][64 + tx * 4];
#pragma unroll
            for (int i = 0; i < 8; ++i)
#pragma unroll
                for (int j = 0; j < 8; ++j)
                    acc[i][j] += a[i] * bb[j];
        }
        __syncthreads();
    }

#pragma unroll
    for (int i = 0; i < 8; ++i) {
        const int r = (i < 4) ? (ty * 4 + i) : (32 + ty * 4 + (i - 4));
        const int n = row0 + r;
#pragma unroll
        for (int jh = 0; jh < 2; ++jh) {
            const int c = (jh == 0) ? (tx * 4) : (64 + tx * 4);
            float4 res;
            res.x = acc[i][jh * 4 + 0];
            res.y = acc[i][jh * 4 + 1];
            res.z = acc[i][jh * 4 + 2];
            res.w = acc[i][jh * 4 + 3];
            *(float4*)(out + ((size_t)b * NN + n) * NC + c) = res;
        }
    }
}

// ---------------------------------------------------------------------------
extern "C" void kernel_launch(void* const* d_in, const int* in_sizes, int n_in,
                              void* d_out, int out_size) {
    const float* x   = (const float*)d_in[0];   // [4,4096,128]
    const float* adj = (const float*)d_in[1];   // [4,4096,4096]
    const float* W   = (const float*)d_in[2];   // [128,384]
    float* out = (float*)d_out;

    (void)in_sizes; (void)n_in; (void)out_size;

    const int SMEM_CHEB = NST * STG;            // 106496 B -> 2 CTAs/SM
    cudaFuncSetAttribute(cheb_mma_kernel,
                         cudaFuncAttributeMaxDynamicSharedMemorySize, SMEM_CHEB);

    degree_partial_cvt_kernel<<<dim3(NN / 128, 16, NB), 128>>>(adj);
    degree_reduce_kernel<<<(NB * NN + 255) / 256, 256>>>();
    x_cvt_kernel<<<(NB * NN * NC + 255) / 256, 256>>>(x);

    // T1 = LR*(deg*x - adj@x) - x       (stashes x->slice0 and T1->bf16)
    cheb_mma_kernel<<<dim3(NN / TM, NB), 256, SMEM_CHEB>>>(x, 0);
    // T2 = 2*(LR*(deg*T1 - adj@T1) - T1) - x
    cheb_mma_kernel<<<dim3(NN / TM, NB), 256, SMEM_CHEB>>>(x, 1);

    out_gemm_kernel<<<dim3(NN / 64, NB), 128>>>(W, out);
}

// round 17
// speedup vs baseline: 1.4490x; 1.0490x over previous
#include <cuda_runtime.h>
#include <cuda_bf16.h>
#include <cstdint>

#define NB 4
#define NN 4096
#define NC 128
#define NKCH 3
#define LRF ((float)(2.0 / (2.0 + 1e-06)))

// ---------------------------------------------------------------------------
// Device scratch. g_Z is [b][k][n][c] contiguous, so the torch
// .view(B,N,-1) of stacked [B,K,N,C] == per-batch rows at stride 384.
// ---------------------------------------------------------------------------
__device__ float         g_Z[(size_t)NB * NKCH * NN * NC];   // 24 MB fp32
__device__ __nv_bfloat16 g_adjh[(size_t)NB * NN * NN];       // 128 MB bf16 adj
__device__ __nv_bfloat16 g_xh[(size_t)NB * NN * NC];         // 4 MB bf16 x
__device__ __nv_bfloat16 g_t1h[(size_t)NB * NN * NC];        // 4 MB bf16 T1
__device__ float g_degpart[16 * NB * NN];
__device__ float g_deg[NB * NN];

// ---------------------------------------------------------------------------
// degree[b,n] = sum_m adj[b,m,n] (exact fp32, deterministic 2-stage),
// fused with adj fp32 -> bf16 conversion (adj is streamed here anyway).
// ---------------------------------------------------------------------------
__global__ void degree_partial_cvt_kernel(const float* __restrict__ adj) {
    const int b   = blockIdx.z;
    const int col = blockIdx.x * 128 + threadIdx.x;
    const int r0  = blockIdx.y * 256;
    const float* A = adj + (size_t)b * NN * NN;
    __nv_bfloat16* Ah = g_adjh + (size_t)b * NN * NN;
    float s = 0.f;
#pragma unroll 8
    for (int m = 0; m < 256; ++m) {
        const float v = A[(size_t)(r0 + m) * NN + col];
        s += v;
        Ah[(size_t)(r0 + m) * NN + col] = __float2bfloat16(v);
    }
    g_degpart[(size_t)blockIdx.y * NB * NN + b * NN + col] = s;
}

__global__ void degree_reduce_kernel() {
    int i = blockIdx.x * blockDim.x + threadIdx.x;
    if (i < NB * NN) {
        float s = 0.f;
#pragma unroll
        for (int r = 0; r < 16; ++r)
            s += g_degpart[(size_t)r * NB * NN + i];
        g_deg[i] = s;
    }
}

// x -> bf16
__global__ void x_cvt_kernel(const float* __restrict__ x) {
    int i = blockIdx.x * blockDim.x + threadIdx.x;
    if (i < NB * NN * NC) g_xh[i] = __float2bfloat16(x[i]);
}

// ---------------------------------------------------------------------------
// Fused Chebyshev step via mma.sync bf16 (m16n8k16, fp32 accumulate):
//   acc = adj[rows] @ Zin                (bf16 inputs, fp32 accum)
//   Zout[n,c] = alpha*( LRF*(deg[n]*Zin_f32[n,c] - acc) - Zin_f32 ) + beta*x
//
// CTA tile 64(m) x 64(c), 128 threads (4 warps, 2m x 2n), warp tile 32x32.
// K chunk 64 (4 k16 steps), 3-stage cp.async ring, 4 CTAs/SM.
// A and B smem rows: 64 bf16 + 8 pad = pitch 72 bf16 (144 B, 16B-aligned),
// ldmatrix phases hit banks 4r -> conflict-free.
// ---------------------------------------------------------------------------
#define TM 64
#define TN 64
#define PROWB 144                     // bytes per smem row (72 bf16)
#define A_BYTES (TM * PROWB)          // 9216
#define STG_SZ (A_BYTES + 64 * PROWB) // 18432
#define NST 3
#define NCH 64

__device__ __forceinline__ void mma_bf16_16x8x16(
    float* d, uint32_t a0, uint32_t a1, uint32_t a2, uint32_t a3,
    uint32_t b0, uint32_t b1)
{
    asm volatile(
        "mma.sync.aligned.m16n8k16.row.col.f32.bf16.bf16.f32 "
        "{%0,%1,%2,%3}, {%4,%5,%6,%7}, {%8,%9}, {%0,%1,%2,%3};"
        : "+f"(d[0]), "+f"(d[1]), "+f"(d[2]), "+f"(d[3])
        : "r"(a0), "r"(a1), "r"(a2), "r"(a3), "r"(b0), "r"(b1));
}

__global__ __launch_bounds__(128, 4)
void cheb_mma_kernel(const float* __restrict__ x, int step)
{
    extern __shared__ char dsm[];

    const int b    = blockIdx.y;
    const int mblk = blockIdx.x >> 1;
    const int nblk = blockIdx.x & 1;
    const int row0 = mblk * TM;
    const int col0 = nblk * TN;
    const int tid  = threadIdx.x;
    const int wid  = tid >> 5;
    const int lid  = tid & 31;
    const int g    = lid >> 2;
    const int tig  = lid & 3;
    const int mbase = (wid & 1) * 32;        // 2 warps along M
    const int nbase = (wid >> 1) * 32;       // 2 warps along N

    const __nv_bfloat16* Arowh = g_adjh + (size_t)b * NN * NN + (size_t)row0 * NN;
    const __nv_bfloat16* Binh  = (step == 0 ? g_xh : g_t1h) + (size_t)b * NN * NC;
    const float* Xb = x + (size_t)b * NN * NC;
    float* Zbase = g_Z + (size_t)b * NKCH * NN * NC;
    const float* Zin_f = (step == 0) ? Xb : (Zbase + (size_t)1 * NN * NC);
    float* Zout = (step == 0) ? (Zbase + (size_t)1 * NN * NC)
                              : (Zbase + (size_t)2 * NN * NC);
    float* Z0 = Zbase;
    __nv_bfloat16* T1h = g_t1h + (size_t)b * NN * NC;
    const float alpha = (step == 0) ? 1.f : 2.f;
    const float beta  = (step == 0) ? 0.f : -1.f;

    uint32_t smem0;
    asm("{ .reg .u64 t; cvta.to.shared.u64 t, %1; cvt.u32.u64 %0, t; }"
        : "=r"(smem0) : "l"(dsm));

    float acc[2][4][4];
#pragma unroll
    for (int mt = 0; mt < 2; ++mt)
#pragma unroll
        for (int nt = 0; nt < 4; ++nt)
#pragma unroll
            for (int q = 0; q < 4; ++q) acc[mt][nt][q] = 0.f;

    auto issue_chunk = [&](int chunk) {
        const uint32_t stg = smem0 + (uint32_t)(chunk % NST) * STG_SZ;
        const int k0 = chunk * 64;
        // A: 64 rows x 64 bf16 (128B) = 512 x 16B chunks, 4/thread
#pragma unroll
        for (int it = 0; it < 4; ++it) {
            const int idx = tid + it * 128;
            const int r = idx >> 3, q = idx & 7;
            const uint32_t da = stg + (uint32_t)r * PROWB + q * 16;
            const __nv_bfloat16* src = Arowh + (size_t)r * NN + k0 + q * 8;
            asm volatile("cp.async.cg.shared.global [%0], [%1], 16;"
                         :: "r"(da), "l"(src));
        }
        // B: 64 rows x 64 bf16 = 512 x 16B chunks, 4/thread
#pragma unroll
        for (int it = 0; it < 4; ++it) {
            const int idx = tid + it * 128;
            const int r = idx >> 3, q = idx & 7;
            const uint32_t db = stg + A_BYTES + (uint32_t)r * PROWB + q * 16;
            const __nv_bfloat16* src = Binh + (size_t)(k0 + r) * NC + col0 + q * 8;
            asm volatile("cp.async.cg.shared.global [%0], [%1], 16;"
                         :: "r"(db), "l"(src));
        }
        asm volatile("cp.async.commit_group;" ::: "memory");
    };

    issue_chunk(0); issue_chunk(1);

    // ldmatrix.x4 per-lane A offset: row = mbase + (l&7) + (l&8), kcol-half = l>>4
    const uint32_t a_lane_off =
        (uint32_t)(mbase + (lid & 7) + ((lid & 8) ? 8 : 0)) * PROWB
        + ((lid & 16) ? 16 : 0);
    const int rowsel = lid & 15;

    for (int c = 0; c < NCH; ++c) {
        if (c < NCH - 1) asm volatile("cp.async.wait_group 1;" ::: "memory");
        else             asm volatile("cp.async.wait_group 0;" ::: "memory");
        __syncthreads();

        if (c + 2 < NCH) issue_chunk(c + 2);

        const uint32_t stg = smem0 + (uint32_t)(c % NST) * STG_SZ;
        const uint32_t abase = stg + a_lane_off;
        const uint32_t bbase = stg + A_BYTES + (uint32_t)rowsel * PROWB;

#pragma unroll
        for (int ks = 0; ks < 4; ++ks) {
            uint32_t a[2][4];
#pragma unroll
            for (int mt = 0; mt < 2; ++mt) {
                const uint32_t aaddr = abase + (uint32_t)mt * (16 * PROWB) + ks * 32;
                asm volatile(
                    "ldmatrix.sync.aligned.m8n8.x4.shared.b16 {%0,%1,%2,%3}, [%4];"
                    : "=r"(a[mt][0]), "=r"(a[mt][1]), "=r"(a[mt][2]), "=r"(a[mt][3])
                    : "r"(aaddr));
            }
#pragma unroll
            for (int nt = 0; nt < 4; ++nt) {
                const int j0 = nbase + nt * 8;
                uint32_t b0, b1;
                const uint32_t baddr = bbase + (uint32_t)(ks * 16) * PROWB + j0 * 2;
                asm volatile(
                    "ldmatrix.sync.aligned.m8n8.x2.trans.shared.b16 {%0, %1}, [%2];"
                    : "=r"(b0), "=r"(b1) : "r"(baddr));
#pragma unroll
                for (int mt = 0; mt < 2; ++mt)
                    mma_bf16_16x8x16(acc[mt][nt], a[mt][0], a[mt][1], a[mt][2], a[mt][3], b0, b1);
            }
        }
    }

    // Fused epilogue (fp32 Zin for the exact deg*z term)
#pragma unroll
    for (int mt = 0; mt < 2; ++mt) {
        const int r0 = row0 + mbase + mt * 16 + g;
        const int r1 = r0 + 8;
        const float dg0 = g_deg[b * NN + r0];
        const float dg1 = g_deg[b * NN + r1];
#pragma unroll
        for (int nt = 0; nt < 4; ++nt) {
            const int c0 = col0 + nbase + nt * 8 + 2 * tig;
            const float2 z0 = *(const float2*)(Zin_f + (size_t)r0 * NC + c0);
            const float2 z1 = *(const float2*)(Zin_f + (size_t)r1 * NC + c0);
            float2 o0, o1;
            o0.x = alpha * (LRF * (dg0 * z0.x - acc[mt][nt][0]) - z0.x);
            o0.y = alpha * (LRF * (dg0 * z0.y - acc[mt][nt][1]) - z0.y);
            o1.x = alpha * (LRF * (dg1 * z1.x - acc[mt][nt][2]) - z1.x);
            o1.y = alpha * (LRF * (dg1 * z1.y - acc[mt][nt][3]) - z1.y);
            if (beta != 0.f) {
                const float2 x0 = *(const float2*)(Xb + (size_t)r0 * NC + c0);
                const float2 x1 = *(const float2*)(Xb + (size_t)r1 * NC + c0);
                o0.x += beta * x0.x; o0.y += beta * x0.y;
                o1.x += beta * x1.x; o1.y += beta * x1.y;
            }
            *(float2*)(Zout + (size_t)r0 * NC + c0) = o0;
            *(float2*)(Zout + (size_t)r1 * NC + c0) = o1;
            if (step == 0) {
                *(float2*)(Z0 + (size_t)r0 * NC + c0) = z0;
                *(float2*)(Z0 + (size_t)r1 * NC + c0) = z1;
                __nv_bfloat162 h0; h0.x = __float2bfloat16(o0.x); h0.y = __float2bfloat16(o0.y);
                __nv_bfloat162 h1; h1.x = __float2bfloat16(o1.x); h1.y = __float2bfloat16(o1.y);
                *(__nv_bfloat162*)(T1h + (size_t)r0 * NC + c0) = h0;
                *(__nv_bfloat162*)(T1h + (size_t)r1 * NC + c0) = h1;
            }
        }
    }
}

// ---------------------------------------------------------------------------
// Final linear: out[b,n,o] = sum_{f<384} Zr[b,n,f] * W[o,f]
//   Zr = per-batch flat g_Z buffer read as rows of stride 384 (view trick).
// 64-row tiles, 128 threads, small smem -> multiple CTAs/SM.
// ---------------------------------------------------------------------------
__global__ __launch_bounds__(128)
void out_gemm_kernel(const float* __restrict__ W, float* __restrict__ out)
{
    const int b    = blockIdx.y;
    const int row0 = blockIdx.x * 64;
    const float* Zr = g_Z + (size_t)b * NKCH * NN * NC + (size_t)row0 * 384;

    __shared__ float As[8][64];
    __shared__ float Bs[8][128];

    const int tid  = threadIdx.x;
    const int tx   = tid & 15;
    const int ty   = tid >> 4;
    const int aRow = tid >> 1;             // 0..63
    const int aCol = (tid & 1) << 2;       // 0 or 4

    float acc[8][8];
#pragma unroll
    for (int i = 0; i < 8; ++i)
#pragma unroll
        for (int j = 0; j < 8; ++j) acc[i][j] = 0.f;

    float4 av = *(const float4*)(Zr + (size_t)aRow * 384 + aCol);
    float bv[8];
#pragma unroll
    for (int e = 0; e < 8; ++e) {
        const int lin = tid + e * 128;
        bv[e] = W[(size_t)(lin & 127) * 384 + (lin >> 7)];
    }

    for (int k0 = 0; k0 < 384; k0 += 8) {
        As[aCol + 0][aRow] = av.x;
        As[aCol + 1][aRow] = av.y;
        As[aCol + 2][aRow] = av.z;
        As[aCol + 3][aRow] = av.w;
#pragma unroll
        for (int e = 0; e < 8; ++e) {
            const int lin = tid + e * 128;
            Bs[lin >> 7][lin & 127] = bv[e];
        }
        __syncthreads();

        if (k0 + 8 < 384) {
            av = *(const float4*)(Zr + (size_t)aRow * 384 + (k0 + 8) + aCol);
#pragma unroll
            for (int e = 0; e < 8; ++e) {
                const int lin = tid + e * 128;
                bv[e] = W[(size_t)(lin & 127) * 384 + (k0 + 8) + (lin >> 7)];
            }
        }

#pragma unroll
        for (int kk = 0; kk < 8; ++kk) {
            float a[8], bb[8];
            *(float4*)&a[0]  = *(const float4*)&As[kk][ty * 4];
            *(float4*)&a[4]  = *(const float4*)&As[kk][32 + ty * 4];
            *(float4*)&bb[0] = *(const float4*)&Bs[kk][tx * 4];
            *(float4*)&bb[4] = *(const float4*)&Bs[kk][64 + tx * 4];
#pragma unroll
            for (int i = 0; i < 8; ++i)
#pragma unroll
                for (int j = 0; j < 8; ++j)
                    acc[i][j] += a[i] * bb[j];
        }
        __syncthreads();
    }

#pragma unroll
    for (int i = 0; i < 8; ++i) {
        const int r = (i < 4) ? (ty * 4 + i) : (32 + ty * 4 + (i - 4));
        const int n = row0 + r;
#pragma unroll
        for (int jh = 0; jh < 2; ++jh) {
            const int c = (jh == 0) ? (tx * 4) : (64 + tx * 4);
            float4 res;
            res.x = acc[i][jh * 4 + 0];
            res.y = acc[i][jh * 4 + 1];
            res.z = acc[i][jh * 4 + 2];
            res.w = acc[i][jh * 4 + 3];
            *(float4*)(out + ((size_t)b * NN + n) * NC + c) = res;
        }
    }
}

// ---------------------------------------------------------------------------
extern "C" void kernel_launch(void* const* d_in, const int* in_sizes, int n_in,
                              void* d_out, int out_size) {
    const float* x   = (const float*)d_in[0];   // [4,4096,128]
    const float* adj = (const float*)d_in[1];   // [4,4096,4096]
    const float* W   = (const float*)d_in[2];   // [128,384]
    float* out = (float*)d_out;

    (void)in_sizes; (void)n_in; (void)out_size;

    const int SMEM_CHEB = NST * STG_SZ;         // 55296 B -> 4 CTAs/SM
    cudaFuncSetAttribute(cheb_mma_kernel,
                         cudaFuncAttributeMaxDynamicSharedMemorySize, SMEM_CHEB);

    degree_partial_cvt_kernel<<<dim3(NN / 128, 16, NB), 128>>>(adj);
    degree_reduce_kernel<<<(NB * NN + 255) / 256, 256>>>();
    x_cvt_kernel<<<(NB * NN * NC + 255) / 256, 256>>>(x);

    // T1 = LR*(deg*x - adj@x) - x       (stashes x->slice0 and T1->bf16)
    cheb_mma_kernel<<<dim3((NN / TM) * (NC / TN), NB), 128, SMEM_CHEB>>>(x, 0);
    // T2 = 2*(LR*(deg*T1 - adj@T1) - T1) - x
    cheb_mma_kernel<<<dim3((NN / TM) * (NC / TN), NB), 128, SMEM_CHEB>>>(x, 1);

    out_gemm_kernel<<<dim3(NN / 64, NB), 128>>>(W, out);
}